// round 13
// baseline (speedup 1.0000x reference)
#include <cuda_runtime.h>
#include <cuda_fp16.h>
#include <math.h>
#include <stdint.h>

#define TT 2048
#define HH 1024
#define FF 1024
#define EE 8

// ---------------- scratch (device globals; no allocation allowed) ----------
__device__ int    g_cnt[EE];
__device__ int    g_tok[EE][TT];
__device__ float  g_wt [EE][TT];
__device__ __half g_acth[EE][TT][FF];   // routed silu(g)*u activations fp16 (32 MB)
__device__ __half g_sacth[TT][FF];      // shared-expert activations fp16 (4 MB)

// ---------------- helpers ---------------------------------------------------
__device__ __forceinline__ uint32_t h2(float x, float y) {
    __half2 h = __floats2half2_rn(x, y);
    return *(uint32_t*)&h;
}
__device__ __forceinline__ uint4 cvt8(float4 a, float4 b) {
    return make_uint4(h2(a.x, a.y), h2(a.z, a.w), h2(b.x, b.y), h2(b.z, b.w));
}
__device__ __forceinline__ uint32_t smem_u32(const void* p) {
    uint32_t a;
    asm("{ .reg .u64 t; cvta.to.shared.u64 t, %1; cvt.u32.u64 %0, t; }"
        : "=r"(a) : "l"(p));
    return a;
}
__device__ __forceinline__ void mma16(float* c, const uint32_t* a, const uint32_t* b) {
    asm volatile(
        "mma.sync.aligned.m16n8k16.row.col.f32.f16.f16.f32 "
        "{%0,%1,%2,%3}, {%4,%5,%6,%7}, {%8,%9}, {%0,%1,%2,%3};"
        : "+f"(c[0]), "+f"(c[1]), "+f"(c[2]), "+f"(c[3])
        : "r"(a[0]), "r"(a[1]), "r"(a[2]), "r"(a[3]), "r"(b[0]), "r"(b[1]));
}
__device__ __forceinline__ void ldsm4(uint32_t* r, uint32_t addr) {
    asm volatile("ldmatrix.sync.aligned.m8n8.x4.shared.b16 {%0,%1,%2,%3}, [%4];"
        : "=r"(r[0]), "=r"(r[1]), "=r"(r[2]), "=r"(r[3]) : "r"(addr));
}
__device__ __forceinline__ void ldsm4t(uint32_t* r, uint32_t addr) {
    asm volatile("ldmatrix.sync.aligned.m8n8.x4.trans.shared.b16 {%0,%1,%2,%3}, [%4];"
        : "=r"(r[0]), "=r"(r[1]), "=r"(r[2]), "=r"(r[3]) : "r"(addr));
}
__device__ __forceinline__ void mbar_init(uint32_t a, uint32_t cnt) {
    asm volatile("mbarrier.init.shared.b64 [%0], %1;" :: "r"(a), "r"(cnt) : "memory");
}
__device__ __forceinline__ void mbar_arrive(uint32_t a) {
    asm volatile("mbarrier.arrive.shared.b64 _, [%0];" :: "r"(a) : "memory");
}
__device__ __forceinline__ void mbar_wait(uint32_t a, uint32_t parity) {
    uint32_t done;
    asm volatile("{\n\t.reg .pred p;\n\t"
                 "mbarrier.try_wait.parity.acquire.cta.shared::cta.b64 p, [%1], %2;\n\t"
                 "selp.b32 %0, 1, 0, p;\n\t}"
                 : "=r"(done) : "r"(a), "r"(parity) : "memory");
    if (!done) {
        asm volatile("{\n\t.reg .pred P1;\n\t"
                     "WL_%=:\n\t"
                     "mbarrier.try_wait.parity.acquire.cta.shared::cta.b64 P1, [%0], %1, 0x989680;\n\t"
                     "@P1 bra.uni WD_%=;\n\t"
                     "bra.uni WL_%=;\n\t"
                     "WD_%=:\n\t}"
                     :: "r"(a), "r"(parity) : "memory");
    }
}

// BK = 64. A rows: 64 fp16 = 128B padded to 144B. B gateup rows: 64 fp16 ->
// 144B. B down rows: 128 fp16 = 256B padded to 272B.
#define ALDR 144
#define GBR  144
#define DBR  272
#define NSTAGE 3
#define NCHUNK 16

// gateup stage: A 128x144=18432 | Bg 64x144=9216 | Bu 9216 -> 36864
#define GU_STAGE 36864
#define GU_BG    18432
#define GU_BU    27648
#define GU_MBAR  110592   // full[3] @ +0, empty[3] @ +24
#define GU_BYTES 110656
// down stage: A 18432 | B 64x272=17408 -> 35840
#define DN_STAGE 35840
#define DN_B     18432
#define DN_MBAR  107520
#define DN_BYTES 107584

// ---------------- init: zero whole output + expert counters ----------------
__global__ void init_kernel(float* __restrict__ out, int out_size) {
    int i = blockIdx.x * blockDim.x + threadIdx.x;
    if (i < EE) g_cnt[i] = 0;
    if (i < out_size) out[i] = 0.0f;
}

// ---------------- router ----------------------------------------------------
__global__ void router_kernel(const float* __restrict__ x,
                              const float* __restrict__ wg) {
    int warp = (blockIdx.x * blockDim.x + threadIdx.x) >> 5;
    int lane = threadIdx.x & 31;
    if (warp >= TT) return;
    const float* xr = x + (size_t)warp * HH;

    float acc[EE];
#pragma unroll
    for (int e = 0; e < EE; e++) acc[e] = 0.0f;
    for (int h = lane; h < HH; h += 32) {
        float xv = xr[h];
        const float4* w4 = (const float4*)(wg + (size_t)h * EE);
        float4 a = w4[0], b = w4[1];
        acc[0] += xv * a.x; acc[1] += xv * a.y;
        acc[2] += xv * a.z; acc[3] += xv * a.w;
        acc[4] += xv * b.x; acc[5] += xv * b.y;
        acc[6] += xv * b.z; acc[7] += xv * b.w;
    }
#pragma unroll
    for (int e = 0; e < EE; e++)
#pragma unroll
        for (int o = 16; o > 0; o >>= 1)
            acc[e] += __shfl_xor_sync(0xffffffffu, acc[e], o);

    if (lane == 0) {
        int i0 = 0; float v0 = acc[0];
#pragma unroll
        for (int e = 1; e < EE; e++) if (acc[e] > v0) { v0 = acc[e]; i0 = e; }
        int i1 = -1; float v1 = -INFINITY;
#pragma unroll
        for (int e = 0; e < EE; e++) {
            if (e == i0) continue;
            if (acc[e] > v1) { v1 = acc[e]; i1 = e; }
        }
        float ex = expf(v1 - v0);
        float inv = 1.0f / (1.0f + ex);
        int p0 = atomicAdd(&g_cnt[i0], 1);
        g_tok[i0][p0] = warp; g_wt[i0][p0] = inv;
        int p1 = atomicAdd(&g_cnt[i1], 1);
        g_tok[i1][p1] = warp; g_wt[i1][p1] = ex * inv;
    }
}

// ---------------- fused gate+up GEMM (routed + shared), fp16, BK=64 --------
// grid (FF/64, TT/128, EE+1); z==EE -> shared expert (dense rows -> g_sacth).
// Block 512: warps 0-7 consumers (4M x 2N, warp 32x32 per matrix),
// warps 8-15 producers (full register prefetch).
__global__ __launch_bounds__(512, 1)
void gemm_gateup(const float* __restrict__ X,
                 const float* __restrict__ Wgp,
                 const float* __restrict__ Wup,
                 const float* __restrict__ Wsg,
                 const float* __restrict__ Wsu) {
    const bool SH = (blockIdx.z == EE);
    const int e   = SH ? 0 : blockIdx.z;
    const int M   = SH ? TT : g_cnt[e];
    const int m0  = blockIdx.y * 128;
    if (m0 >= M) return;
    const int n0  = blockIdx.x * 64;

    const float* Wg = SH ? Wsg : (Wgp + (size_t)e * HH * FF);
    const float* Wu = SH ? Wsu : (Wup + (size_t)e * HH * FF);

    extern __shared__ char smem[];
    const uint32_t sbase = smem_u32(smem);
    const int tid = threadIdx.x;
    const int wid = tid >> 5, lane = tid & 31;

    const uint32_t mb_full  = sbase + GU_MBAR;
    const uint32_t mb_empty = sbase + GU_MBAR + 24;
    if (tid == 0) {
#pragma unroll
        for (int s = 0; s < NSTAGE; s++) {
            mbar_init(mb_full  + 8 * s, 8);   // 8 producer warps
            mbar_init(mb_empty + 8 * s, 8);   // 8 consumer warps
        }
    }
    __syncthreads();

    if (wid < 8) {
        // ================= consumer =================
        const int wm = wid >> 1, wn = wid & 1;
        const int grp = lane >> 2, qid = lane & 3;
        uint32_t aoff[2], boff[2];
#pragma unroll
        for (int mt = 0; mt < 2; mt++)
            aoff[mt] = (wm * 32 + mt * 16 + (lane & 15)) * ALDR + ((lane & 16) ? 16 : 0);
#pragma unroll
        for (int nb = 0; nb < 2; nb++)
            boff[nb] = (lane & 15) * GBR + (wn * 32 + nb * 16) * 2 + ((lane & 16) ? 16 : 0);

        float cg[2][4][4], cu[2][4][4];
#pragma unroll
        for (int mt = 0; mt < 2; mt++)
#pragma unroll
            for (int nt = 0; nt < 4; nt++)
#pragma unroll
                for (int i = 0; i < 4; i++) { cg[mt][nt][i] = 0.0f; cu[mt][nt][i] = 0.0f; }

        int s = 0, ph = 0;
        for (int c = 0; c < NCHUNK; c++) {
            mbar_wait(mb_full + 8 * s, ph);
            const uint32_t Ab = sbase + s * GU_STAGE;
            const uint32_t Gb = Ab + GU_BG;
            const uint32_t Ub = Ab + GU_BU;
#pragma unroll
            for (int ks = 0; ks < 4; ks++) {     // four k16 steps
                uint32_t a[2][4];
                ldsm4(a[0], Ab + aoff[0] + ks * 32);
                ldsm4(a[1], Ab + aoff[1] + ks * 32);
#pragma unroll
                for (int nb = 0; nb < 2; nb++) {
                    uint32_t bg[4], bu[4];
                    ldsm4t(bg, Gb + boff[nb] + ks * 16 * GBR);
                    mma16(cg[0][nb * 2 + 0], a[0], &bg[0]);
                    mma16(cg[0][nb * 2 + 1], a[0], &bg[2]);
                    mma16(cg[1][nb * 2 + 0], a[1], &bg[0]);
                    mma16(cg[1][nb * 2 + 1], a[1], &bg[2]);
                    ldsm4t(bu, Ub + boff[nb] + ks * 16 * GBR);
                    mma16(cu[0][nb * 2 + 0], a[0], &bu[0]);
                    mma16(cu[0][nb * 2 + 1], a[0], &bu[2]);
                    mma16(cu[1][nb * 2 + 0], a[1], &bu[0]);
                    mma16(cu[1][nb * 2 + 1], a[1], &bu[2]);
                }
            }
            __syncwarp();
            if (lane == 0) mbar_arrive(mb_empty + 8 * s);
            if (++s == NSTAGE) { s = 0; ph ^= 1; }
        }

        // epilogue: silu(g)*u -> fp16
#pragma unroll
        for (int mt = 0; mt < 2; mt++) {
#pragma unroll
            for (int half = 0; half < 2; half++) {
                int m = m0 + wm * 32 + mt * 16 + grp + half * 8;
                if (m >= M) continue;
                __half* orow = SH ? &g_sacth[m][0] : &g_acth[e][m][0];
#pragma unroll
                for (int nt = 0; nt < 4; nt++) {
                    int c0 = n0 + wn * 32 + nt * 8 + 2 * qid;
                    float g0 = cg[mt][nt][half * 2 + 0], u0 = cu[mt][nt][half * 2 + 0];
                    float g1 = cg[mt][nt][half * 2 + 1], u1 = cu[mt][nt][half * 2 + 1];
                    float o0 = (g0 / (1.0f + expf(-g0))) * u0;
                    float o1 = (g1 / (1.0f + expf(-g1))) * u1;
                    *(uint32_t*)&orow[c0] = h2(o0, o1);
                }
            }
        }
    } else {
        // ================= producer =================
        const int ptid = tid - 256;           // 0..255
        // A: 2 threads per row; 32 floats each
        const int arow = ptid >> 1;           // 0..127
        const int ah   = ptid & 1;
        const float* aptr = nullptr;
        if (m0 + arow < M) {
            int tok = SH ? (m0 + arow) : g_tok[e][m0 + arow];
            aptr = X + (size_t)tok * HH + ah * 32;
        }
        // B: 4 threads per k-row; 16 floats each per matrix
        const int bkr = ptid >> 2;            // 0..63
        const int bq  = (ptid & 3) * 16;
        const float* gp = Wg + (size_t)bkr * FF + n0 + bq;
        const float* up = Wu + (size_t)bkr * FF + n0 + bq;

        int s = 0, ph = 1;   // first empty-wait passes immediately
        for (int c = 0; c < NCHUNK; c++) {
            const int kk = c * 64;
            float4 av[8], gv[4], uv[4];
#pragma unroll
            for (int i = 0; i < 8; i++)
                av[i] = aptr ? *(const float4*)(aptr + kk + 4 * i) : make_float4(0,0,0,0);
#pragma unroll
            for (int i = 0; i < 4; i++) {
                gv[i] = *(const float4*)(gp + (size_t)kk * FF + 4 * i);
                uv[i] = *(const float4*)(up + (size_t)kk * FF + 4 * i);
            }
            mbar_wait(mb_empty + 8 * s, ph);
            char* Ast = smem + s * GU_STAGE;
#pragma unroll
            for (int i = 0; i < 4; i++)
                *(uint4*)(Ast + arow * ALDR + ah * 64 + i * 16) = cvt8(av[2*i], av[2*i+1]);
            char* Gst = Ast + GU_BG;
            char* Ust = Ast + GU_BU;
#pragma unroll
            for (int i = 0; i < 2; i++) {
                *(uint4*)(Gst + bkr * GBR + bq * 2 + i * 16) = cvt8(gv[2*i], gv[2*i+1]);
                *(uint4*)(Ust + bkr * GBR + bq * 2 + i * 16) = cvt8(uv[2*i], uv[2*i+1]);
            }
            __syncwarp();
            if (lane == 0) mbar_arrive(mb_full + 8 * s);
            if (++s == NSTAGE) { s = 0; ph ^= 1; }
        }
    }
}

// ---------------- down-proj GEMM (routed + shared), fp16 A, BK=64 ----------
// grid (HH/128, TT/128, EE+1); z==EE -> shared expert (A=g_sacth, weight 1).
// All paths atomicAdd into pre-zeroed out.
__global__ __launch_bounds__(512, 1)
void gemm_down(const float* __restrict__ Wdp,
               const float* __restrict__ Wsd,
               float* __restrict__ out) {
    const bool SH = (blockIdx.z == EE);
    const int e   = SH ? 0 : blockIdx.z;
    const int M   = SH ? TT : g_cnt[e];
    const int m0  = blockIdx.y * 128;
    if (m0 >= M) return;
    const int n0  = blockIdx.x * 128;

    const float*  Wd     = SH ? Wsd : (Wdp + (size_t)e * FF * HH);
    const __half* Asrc_h = SH ? &g_sacth[0][0] : &g_acth[e][0][0];

    extern __shared__ char smem[];
    const uint32_t sbase = smem_u32(smem);
    const int tid = threadIdx.x;
    const int wid = tid >> 5, lane = tid & 31;

    const uint32_t mb_full  = sbase + DN_MBAR;
    const uint32_t mb_empty = sbase + DN_MBAR + 24;
    if (tid == 0) {
#pragma unroll
        for (int s = 0; s < NSTAGE; s++) {
            mbar_init(mb_full  + 8 * s, 8);
            mbar_init(mb_empty + 8 * s, 8);
        }
    }
    __syncthreads();

    if (wid < 8) {
        // ================= consumer =================
        const int wm = wid >> 1, wn = wid & 1;
        const int grp = lane >> 2, qid = lane & 3;
        uint32_t aoff[2], boff[4];
#pragma unroll
        for (int mt = 0; mt < 2; mt++)
            aoff[mt] = (wm * 32 + mt * 16 + (lane & 15)) * ALDR + ((lane & 16) ? 16 : 0);
#pragma unroll
        for (int nb = 0; nb < 4; nb++)
            boff[nb] = (lane & 15) * DBR + (wn * 64 + nb * 16) * 2 + ((lane & 16) ? 16 : 0);

        float cc[2][8][4];
#pragma unroll
        for (int mt = 0; mt < 2; mt++)
#pragma unroll
            for (int nt = 0; nt < 8; nt++)
#pragma unroll
                for (int i = 0; i < 4; i++) cc[mt][nt][i] = 0.0f;

        int s = 0, ph = 0;
        for (int c = 0; c < NCHUNK; c++) {
            mbar_wait(mb_full + 8 * s, ph);
            const uint32_t Ab = sbase + s * DN_STAGE;
            const uint32_t Bb = Ab + DN_B;
#pragma unroll
            for (int ks = 0; ks < 4; ks++) {
                uint32_t a[2][4];
                ldsm4(a[0], Ab + aoff[0] + ks * 32);
                ldsm4(a[1], Ab + aoff[1] + ks * 32);
#pragma unroll
                for (int nb = 0; nb < 4; nb++) {
                    uint32_t b_[4];
                    ldsm4t(b_, Bb + boff[nb] + ks * 16 * DBR);
                    mma16(cc[0][nb * 2 + 0], a[0], &b_[0]);
                    mma16(cc[0][nb * 2 + 1], a[0], &b_[2]);
                    mma16(cc[1][nb * 2 + 0], a[1], &b_[0]);
                    mma16(cc[1][nb * 2 + 1], a[1], &b_[2]);
                }
            }
            __syncwarp();
            if (lane == 0) mbar_arrive(mb_empty + 8 * s);
            if (++s == NSTAGE) { s = 0; ph ^= 1; }
        }

#pragma unroll
        for (int mt = 0; mt < 2; mt++) {
#pragma unroll
            for (int half = 0; half < 2; half++) {
                int m = m0 + wm * 32 + mt * 16 + grp + half * 8;
                if (m >= M) continue;
                int tok  = SH ? m : g_tok[e][m];
                float w  = SH ? 1.0f : g_wt[e][m];
                float* orow = out + (size_t)tok * HH;
#pragma unroll
                for (int nt = 0; nt < 8; nt++) {
                    int c0 = n0 + wn * 64 + nt * 8 + 2 * qid;
                    atomicAdd(&orow[c0],     w * cc[mt][nt][half * 2 + 0]);
                    atomicAdd(&orow[c0 + 1], w * cc[mt][nt][half * 2 + 1]);
                }
            }
        }
    } else {
        // ================= producer =================
        const int ptid = tid - 256;
        // A (fp16 source): 2 threads per row; 32 halfs = 64B each
        const int arow = ptid >> 1;
        const int ah   = ptid & 1;
        const __half* aptr = (m0 + arow < M)
            ? (Asrc_h + (size_t)(m0 + arow) * FF + ah * 32) : nullptr;
        // B: 4 threads per k-row; 32 floats each
        const int bkr = ptid >> 2;
        const int bq  = (ptid & 3) * 32;
        const float* wp = Wd + (size_t)bkr * HH + n0 + bq;

        int s = 0, ph = 1;
        for (int c = 0; c < NCHUNK; c++) {
            const int kk = c * 64;
            uint4 av[4];                        // 64 bytes = 32 halfs (FIXED: was [2])
            float4 bv[8];
#pragma unroll
            for (int i = 0; i < 4; i++)
                av[i] = aptr ? *(const uint4*)((const char*)(aptr + kk) + i * 16)
                             : make_uint4(0, 0, 0, 0);
#pragma unroll
            for (int i = 0; i < 8; i++)
                bv[i] = *(const float4*)(wp + (size_t)kk * HH + 4 * i);

            mbar_wait(mb_empty + 8 * s, ph);
            char* Ast = smem + s * DN_STAGE;
#pragma unroll
            for (int i = 0; i < 4; i++)
                *(uint4*)(Ast + arow * ALDR + ah * 64 + i * 16) = av[i];
            char* Bst = Ast + DN_B;
#pragma unroll
            for (int i = 0; i < 4; i++)
                *(uint4*)(Bst + bkr * DBR + bq * 2 + i * 16) = cvt8(bv[2*i], bv[2*i+1]);
            __syncwarp();
            if (lane == 0) mbar_arrive(mb_full + 8 * s);
            if (++s == NSTAGE) { s = 0; ph ^= 1; }
        }
    }
}

// ---------------- launch ---------------------------------------------------
extern "C" void kernel_launch(void* const* d_in, const int* in_sizes, int n_in,
                              void* d_out, int out_size) {
    const float* x   = (const float*)d_in[0];
    const float* wg  = (const float*)d_in[1];
    const float* wgp = (const float*)d_in[2];
    const float* wup = (const float*)d_in[3];
    const float* wdp = (const float*)d_in[4];
    const float* wsg = (const float*)d_in[5];
    const float* wsu = (const float*)d_in[6];
    const float* wsd = (const float*)d_in[7];
    float* out = (float*)d_out;

    cudaFuncSetAttribute(gemm_gateup, cudaFuncAttributeMaxDynamicSharedMemorySize, GU_BYTES);
    cudaFuncSetAttribute(gemm_down,   cudaFuncAttributeMaxDynamicSharedMemorySize, DN_BYTES);

    init_kernel<<<(out_size + 255) / 256, 256>>>(out, out_size);

    router_kernel<<<TT / 8, 256>>>(x, wg);

    dim3 g1(FF / 64, TT / 128, EE + 1);
    gemm_gateup<<<g1, 512, GU_BYTES>>>(x, wgp, wup, wsg, wsu);

    dim3 g2(HH / 128, TT / 128, EE + 1);
    gemm_down<<<g2, 512, DN_BYTES>>>(wdp, wsd, out);
}

// round 14
// speedup vs baseline: 1.1748x; 1.1748x over previous
#include <cuda_runtime.h>
#include <cuda_fp16.h>
#include <math.h>
#include <stdint.h>

#define TT 2048
#define HH 1024
#define FF 1024
#define EE 8

// ---------------- scratch (device globals; no allocation allowed) ----------
__device__ int    g_cnt[EE];
__device__ int    g_tok[EE][TT];
__device__ float  g_wt [EE][TT];
__device__ __half g_acth[EE][TT][FF];   // routed silu(g)*u activations fp16 (32 MB)
__device__ __half g_sacth[TT][FF];      // shared-expert activations fp16 (4 MB)

// ---------------- helpers ---------------------------------------------------
__device__ __forceinline__ uint32_t h2(float x, float y) {
    __half2 h = __floats2half2_rn(x, y);
    return *(uint32_t*)&h;
}
__device__ __forceinline__ uint4 cvt8(float4 a, float4 b) {
    return make_uint4(h2(a.x, a.y), h2(a.z, a.w), h2(b.x, b.y), h2(b.z, b.w));
}
__device__ __forceinline__ uint32_t smem_u32(const void* p) {
    uint32_t a;
    asm("{ .reg .u64 t; cvta.to.shared.u64 t, %1; cvt.u32.u64 %0, t; }"
        : "=r"(a) : "l"(p));
    return a;
}
__device__ __forceinline__ void mma16(float* c, const uint32_t* a, const uint32_t* b) {
    asm volatile(
        "mma.sync.aligned.m16n8k16.row.col.f32.f16.f16.f32 "
        "{%0,%1,%2,%3}, {%4,%5,%6,%7}, {%8,%9}, {%0,%1,%2,%3};"
        : "+f"(c[0]), "+f"(c[1]), "+f"(c[2]), "+f"(c[3])
        : "r"(a[0]), "r"(a[1]), "r"(a[2]), "r"(a[3]), "r"(b[0]), "r"(b[1]));
}
__device__ __forceinline__ void ldsm4(uint32_t* r, uint32_t addr) {
    asm volatile("ldmatrix.sync.aligned.m8n8.x4.shared.b16 {%0,%1,%2,%3}, [%4];"
        : "=r"(r[0]), "=r"(r[1]), "=r"(r[2]), "=r"(r[3]) : "r"(addr));
}
__device__ __forceinline__ void ldsm4t(uint32_t* r, uint32_t addr) {
    asm volatile("ldmatrix.sync.aligned.m8n8.x4.trans.shared.b16 {%0,%1,%2,%3}, [%4];"
        : "=r"(r[0]), "=r"(r[1]), "=r"(r[2]), "=r"(r[3]) : "r"(addr));
}
__device__ __forceinline__ void mbar_init(uint32_t a, uint32_t cnt) {
    asm volatile("mbarrier.init.shared.b64 [%0], %1;" :: "r"(a), "r"(cnt) : "memory");
}
__device__ __forceinline__ void mbar_arrive(uint32_t a) {
    asm volatile("mbarrier.arrive.shared.b64 _, [%0];" :: "r"(a) : "memory");
}
__device__ __forceinline__ void mbar_wait(uint32_t a, uint32_t parity) {
    uint32_t done;
    asm volatile("{\n\t.reg .pred p;\n\t"
                 "mbarrier.try_wait.parity.acquire.cta.shared::cta.b64 p, [%1], %2;\n\t"
                 "selp.b32 %0, 1, 0, p;\n\t}"
                 : "=r"(done) : "r"(a), "r"(parity) : "memory");
    if (!done) {
        asm volatile("{\n\t.reg .pred P1;\n\t"
                     "WL_%=:\n\t"
                     "mbarrier.try_wait.parity.acquire.cta.shared::cta.b64 P1, [%0], %1, 0x989680;\n\t"
                     "@P1 bra.uni WD_%=;\n\t"
                     "bra.uni WL_%=;\n\t"
                     "WD_%=:\n\t}"
                     :: "r"(a), "r"(parity) : "memory");
    }
}

// BK = 32. A rows: 32 fp16 = 64B padded to 80B (LDSM conflict-free).
// Gateup B rows: 64 fp16 = 128B padded to 144B. Down B rows: 128 fp16 = 256B
// padded to 272B.
#define ALDR 80
#define GBR  144
#define DBR  272
#define NSTAGE 4
#define NCHUNK 32

// gateup stage: A 128x80=10240 | Bg 32x144=4608 | Bu 4608 -> 19456
#define GU_STAGE 19456
#define GU_BG    10240
#define GU_BU    14848
#define GU_MBAR  77824    // full[4] @ +0, empty[4] @ +32
#define GU_BYTES 77888
// down stage: A 10240 | B 32x272=8704 -> 18944
#define DN_STAGE 18944
#define DN_B     10240
#define DN_MBAR  75776
#define DN_BYTES 75840

// ---------------- init: zero counters + tail (aux_loss) --------------------
__global__ void init_kernel(float* __restrict__ out, int out_size) {
    int i = blockIdx.x * blockDim.x + threadIdx.x;
    if (i < EE) g_cnt[i] = 0;
    int tail = out_size - TT * HH;
    if (i < tail) out[TT * HH + i] = 0.0f;
}

// ---------------- router ----------------------------------------------------
__global__ void router_kernel(const float* __restrict__ x,
                              const float* __restrict__ wg) {
    int warp = (blockIdx.x * blockDim.x + threadIdx.x) >> 5;
    int lane = threadIdx.x & 31;
    if (warp >= TT) return;
    const float* xr = x + (size_t)warp * HH;

    float acc[EE];
#pragma unroll
    for (int e = 0; e < EE; e++) acc[e] = 0.0f;
    for (int h = lane; h < HH; h += 32) {
        float xv = xr[h];
        const float4* w4 = (const float4*)(wg + (size_t)h * EE);
        float4 a = w4[0], b = w4[1];
        acc[0] += xv * a.x; acc[1] += xv * a.y;
        acc[2] += xv * a.z; acc[3] += xv * a.w;
        acc[4] += xv * b.x; acc[5] += xv * b.y;
        acc[6] += xv * b.z; acc[7] += xv * b.w;
    }
#pragma unroll
    for (int e = 0; e < EE; e++)
#pragma unroll
        for (int o = 16; o > 0; o >>= 1)
            acc[e] += __shfl_xor_sync(0xffffffffu, acc[e], o);

    if (lane == 0) {
        int i0 = 0; float v0 = acc[0];
#pragma unroll
        for (int e = 1; e < EE; e++) if (acc[e] > v0) { v0 = acc[e]; i0 = e; }
        int i1 = -1; float v1 = -INFINITY;
#pragma unroll
        for (int e = 0; e < EE; e++) {
            if (e == i0) continue;
            if (acc[e] > v1) { v1 = acc[e]; i1 = e; }
        }
        float ex = expf(v1 - v0);
        float inv = 1.0f / (1.0f + ex);
        int p0 = atomicAdd(&g_cnt[i0], 1);
        g_tok[i0][p0] = warp; g_wt[i0][p0] = inv;
        int p1 = atomicAdd(&g_cnt[i1], 1);
        g_tok[i1][p1] = warp; g_wt[i1][p1] = ex * inv;
    }
}

// ---------------- fused gate+up GEMM (routed + shared), fp16, BK=32 --------
// grid (FF/64, TT/128, EE+1); z==EE -> shared expert (dense rows -> g_sacth).
// 384 threads: warps 0-7 consumers (4M x 2N, warp 32x32 per matrix),
// warps 8-11 producers.
__global__ __launch_bounds__(384, 1)
void gemm_gateup(const float* __restrict__ X,
                 const float* __restrict__ Wgp,
                 const float* __restrict__ Wup,
                 const float* __restrict__ Wsg,
                 const float* __restrict__ Wsu) {
    const bool SH = (blockIdx.z == EE);
    const int e   = SH ? 0 : blockIdx.z;
    const int M   = SH ? TT : g_cnt[e];
    const int m0  = blockIdx.y * 128;
    if (m0 >= M) return;
    const int n0  = blockIdx.x * 64;

    const float* Wg = SH ? Wsg : (Wgp + (size_t)e * HH * FF);
    const float* Wu = SH ? Wsu : (Wup + (size_t)e * HH * FF);

    extern __shared__ char smem[];
    const uint32_t sbase = smem_u32(smem);
    const int tid = threadIdx.x;
    const int wid = tid >> 5, lane = tid & 31;

    const uint32_t mb_full  = sbase + GU_MBAR;
    const uint32_t mb_empty = sbase + GU_MBAR + 32;
    if (tid == 0) {
#pragma unroll
        for (int s = 0; s < NSTAGE; s++) {
            mbar_init(mb_full  + 8 * s, 4);   // 4 producer warps
            mbar_init(mb_empty + 8 * s, 8);   // 8 consumer warps
        }
    }
    __syncthreads();

    if (wid < 8) {
        // ================= consumer =================
        const int wm = wid >> 1, wn = wid & 1;
        const int grp = lane >> 2, qid = lane & 3;
        uint32_t aoff[2], boff[2];
#pragma unroll
        for (int mt = 0; mt < 2; mt++)
            aoff[mt] = (wm * 32 + mt * 16 + (lane & 15)) * ALDR + ((lane & 16) ? 16 : 0);
#pragma unroll
        for (int nb = 0; nb < 2; nb++)
            boff[nb] = (lane & 15) * GBR + (wn * 32 + nb * 16) * 2 + ((lane & 16) ? 16 : 0);

        float cg[2][4][4], cu[2][4][4];
#pragma unroll
        for (int mt = 0; mt < 2; mt++)
#pragma unroll
            for (int nt = 0; nt < 4; nt++)
#pragma unroll
                for (int i = 0; i < 4; i++) { cg[mt][nt][i] = 0.0f; cu[mt][nt][i] = 0.0f; }

        int s = 0, ph = 0;
        for (int c = 0; c < NCHUNK; c++) {
            mbar_wait(mb_full + 8 * s, ph);
            const uint32_t Ab = sbase + s * GU_STAGE;
            const uint32_t Gb = Ab + GU_BG;
            const uint32_t Ub = Ab + GU_BU;
#pragma unroll
            for (int ks = 0; ks < 2; ks++) {     // two k16 steps
                uint32_t a[2][4];
                ldsm4(a[0], Ab + aoff[0] + ks * 32);
                ldsm4(a[1], Ab + aoff[1] + ks * 32);
#pragma unroll
                for (int nb = 0; nb < 2; nb++) {
                    uint32_t bg[4], bu[4];
                    ldsm4t(bg, Gb + boff[nb] + ks * 16 * GBR);
                    mma16(cg[0][nb * 2 + 0], a[0], &bg[0]);
                    mma16(cg[0][nb * 2 + 1], a[0], &bg[2]);
                    mma16(cg[1][nb * 2 + 0], a[1], &bg[0]);
                    mma16(cg[1][nb * 2 + 1], a[1], &bg[2]);
                    ldsm4t(bu, Ub + boff[nb] + ks * 16 * GBR);
                    mma16(cu[0][nb * 2 + 0], a[0], &bu[0]);
                    mma16(cu[0][nb * 2 + 1], a[0], &bu[2]);
                    mma16(cu[1][nb * 2 + 0], a[1], &bu[0]);
                    mma16(cu[1][nb * 2 + 1], a[1], &bu[2]);
                }
            }
            __syncwarp();
            if (lane == 0) mbar_arrive(mb_empty + 8 * s);
            if (++s == NSTAGE) { s = 0; ph ^= 1; }
        }

        // epilogue: silu(g)*u -> fp16
#pragma unroll
        for (int mt = 0; mt < 2; mt++) {
#pragma unroll
            for (int half = 0; half < 2; half++) {
                int m = m0 + wm * 32 + mt * 16 + grp + half * 8;
                if (m >= M) continue;
                __half* orow = SH ? &g_sacth[m][0] : &g_acth[e][m][0];
#pragma unroll
                for (int nt = 0; nt < 4; nt++) {
                    int c0 = n0 + wn * 32 + nt * 8 + 2 * qid;
                    float g0 = cg[mt][nt][half * 2 + 0], u0 = cu[mt][nt][half * 2 + 0];
                    float g1 = cg[mt][nt][half * 2 + 1], u1 = cu[mt][nt][half * 2 + 1];
                    float o0 = (g0 / (1.0f + expf(-g0))) * u0;
                    float o1 = (g1 / (1.0f + expf(-g1))) * u1;
                    *(uint32_t*)&orow[c0] = h2(o0, o1);
                }
            }
        }
    } else {
        // ================= producer (128 threads) =================
        const int ptid = tid - 256;           // 0..127
        const int base = ptid >> 2;           // 0..31
        const int q    = ptid & 3;

        // A: 4 rows per thread (base + 32*i), floats [q*8, q*8+8)
        const float* ap[4];
#pragma unroll
        for (int i = 0; i < 4; i++) {
            int r = m0 + base + 32 * i;
            if (r < M) {
                int tok = SH ? r : g_tok[e][r];
                ap[i] = X + (size_t)tok * HH + q * 8;
            } else ap[i] = nullptr;
        }
        // B: k-row = base, floats [q*16, q*16+16) per matrix
        const float* gp = Wg + (size_t)base * FF + n0 + q * 16;
        const float* up = Wu + (size_t)base * FF + n0 + q * 16;

        int s = 0, ph = 1;   // first empty-wait passes immediately
        for (int c = 0; c < NCHUNK; c++) {
            const int kk = c * 32;
            float4 av[4][2], gv[4], uv[4];
#pragma unroll
            for (int i = 0; i < 4; i++) {
                av[i][0] = ap[i] ? *(const float4*)(ap[i] + kk)     : make_float4(0,0,0,0);
                av[i][1] = ap[i] ? *(const float4*)(ap[i] + kk + 4) : make_float4(0,0,0,0);
            }
#pragma unroll
            for (int i = 0; i < 4; i++) {
                gv[i] = *(const float4*)(gp + (size_t)kk * FF + 4 * i);
                uv[i] = *(const float4*)(up + (size_t)kk * FF + 4 * i);
            }
            mbar_wait(mb_empty + 8 * s, ph);
            char* Ast = smem + s * GU_STAGE;
#pragma unroll
            for (int i = 0; i < 4; i++) {
                int row = base + 32 * i;
                *(uint4*)(Ast + row * ALDR + q * 16) = cvt8(av[i][0], av[i][1]);
            }
            char* Gst = Ast + GU_BG;
            char* Ust = Ast + GU_BU;
#pragma unroll
            for (int i = 0; i < 2; i++) {
                *(uint4*)(Gst + base * GBR + q * 32 + i * 16) = cvt8(gv[2*i], gv[2*i+1]);
                *(uint4*)(Ust + base * GBR + q * 32 + i * 16) = cvt8(uv[2*i], uv[2*i+1]);
            }
            __syncwarp();
            if (lane == 0) mbar_arrive(mb_full + 8 * s);
            if (++s == NSTAGE) { s = 0; ph ^= 1; }
        }
    }
}

// ---------------- down-proj GEMM, fp16 A, BK=32 ----------------------------
// EXPERT: A = g_acth[e], weighted atomicAdd. !EXPERT: A = g_sacth, plain
// store (initializes out). Block 128(M) x 128(N), consumers 4M x 2N (32x64).
template <bool EXPERT>
__global__ __launch_bounds__(384, 1)
void gemm_down(const float* __restrict__ Wd_all,
               float* __restrict__ out) {
    const int e  = EXPERT ? blockIdx.z : 0;
    const int M  = EXPERT ? g_cnt[e] : TT;
    const int m0 = blockIdx.y * 128;
    if (m0 >= M) return;
    const int n0 = blockIdx.x * 128;

    const float*  Wd     = Wd_all + (EXPERT ? (size_t)e * FF * HH : 0);
    const __half* Asrc_h = EXPERT ? &g_acth[e][0][0] : &g_sacth[0][0];

    extern __shared__ char smem[];
    const uint32_t sbase = smem_u32(smem);
    const int tid = threadIdx.x;
    const int wid = tid >> 5, lane = tid & 31;

    const uint32_t mb_full  = sbase + DN_MBAR;
    const uint32_t mb_empty = sbase + DN_MBAR + 32;
    if (tid == 0) {
#pragma unroll
        for (int s = 0; s < NSTAGE; s++) {
            mbar_init(mb_full  + 8 * s, 4);
            mbar_init(mb_empty + 8 * s, 8);
        }
    }
    __syncthreads();

    if (wid < 8) {
        // ================= consumer =================
        const int wm = wid >> 1, wn = wid & 1;
        const int grp = lane >> 2, qid = lane & 3;
        uint32_t aoff[2], boff[4];
#pragma unroll
        for (int mt = 0; mt < 2; mt++)
            aoff[mt] = (wm * 32 + mt * 16 + (lane & 15)) * ALDR + ((lane & 16) ? 16 : 0);
#pragma unroll
        for (int nb = 0; nb < 4; nb++)
            boff[nb] = (lane & 15) * DBR + (wn * 64 + nb * 16) * 2 + ((lane & 16) ? 16 : 0);

        float cc[2][8][4];
#pragma unroll
        for (int mt = 0; mt < 2; mt++)
#pragma unroll
            for (int nt = 0; nt < 8; nt++)
#pragma unroll
                for (int i = 0; i < 4; i++) cc[mt][nt][i] = 0.0f;

        int s = 0, ph = 0;
        for (int c = 0; c < NCHUNK; c++) {
            mbar_wait(mb_full + 8 * s, ph);
            const uint32_t Ab = sbase + s * DN_STAGE;
            const uint32_t Bb = Ab + DN_B;
#pragma unroll
            for (int ks = 0; ks < 2; ks++) {
                uint32_t a[2][4];
                ldsm4(a[0], Ab + aoff[0] + ks * 32);
                ldsm4(a[1], Ab + aoff[1] + ks * 32);
#pragma unroll
                for (int nb = 0; nb < 4; nb++) {
                    uint32_t b_[4];
                    ldsm4t(b_, Bb + boff[nb] + ks * 16 * DBR);
                    mma16(cc[0][nb * 2 + 0], a[0], &b_[0]);
                    mma16(cc[0][nb * 2 + 1], a[0], &b_[2]);
                    mma16(cc[1][nb * 2 + 0], a[1], &b_[0]);
                    mma16(cc[1][nb * 2 + 1], a[1], &b_[2]);
                }
            }
            __syncwarp();
            if (lane == 0) mbar_arrive(mb_empty + 8 * s);
            if (++s == NSTAGE) { s = 0; ph ^= 1; }
        }

#pragma unroll
        for (int mt = 0; mt < 2; mt++) {
#pragma unroll
            for (int half = 0; half < 2; half++) {
                int m = m0 + wm * 32 + mt * 16 + grp + half * 8;
                if (m >= M) continue;
                if (EXPERT) {
                    int tok = g_tok[e][m];
                    float w = g_wt[e][m];
                    float* orow = out + (size_t)tok * HH;
#pragma unroll
                    for (int nt = 0; nt < 8; nt++) {
                        int c0 = n0 + wn * 64 + nt * 8 + 2 * qid;
                        atomicAdd(&orow[c0],     w * cc[mt][nt][half * 2 + 0]);
                        atomicAdd(&orow[c0 + 1], w * cc[mt][nt][half * 2 + 1]);
                    }
                } else {
                    float* orow = out + (size_t)m * HH;
#pragma unroll
                    for (int nt = 0; nt < 8; nt++) {
                        int c0 = n0 + wn * 64 + nt * 8 + 2 * qid;
                        float2 o = make_float2(cc[mt][nt][half * 2 + 0],
                                               cc[mt][nt][half * 2 + 1]);
                        *(float2*)&orow[c0] = o;
                    }
                }
            }
        }
    } else {
        // ================= producer (128 threads) =================
        const int ptid = tid - 256;
        const int base = ptid >> 2;           // 0..31
        const int q    = ptid & 3;

        // A (fp16 source): 4 rows per thread, halfs [q*8, q*8+8) = 16B each
        const __half* ap[4];
#pragma unroll
        for (int i = 0; i < 4; i++) {
            int r = m0 + base + 32 * i;
            ap[i] = (r < M) ? (Asrc_h + (size_t)r * FF + q * 8) : nullptr;
        }
        // B: k-row = base, floats [q*32, q*32+32)
        const float* wp = Wd + (size_t)base * HH + n0 + q * 32;

        int s = 0, ph = 1;
        for (int c = 0; c < NCHUNK; c++) {
            const int kk = c * 32;
            uint4 av[4];
            float4 bv[8];
#pragma unroll
            for (int i = 0; i < 4; i++)
                av[i] = ap[i] ? *(const uint4*)(ap[i] + kk) : make_uint4(0, 0, 0, 0);
#pragma unroll
            for (int i = 0; i < 8; i++)
                bv[i] = *(const float4*)(wp + (size_t)kk * HH + 4 * i);

            mbar_wait(mb_empty + 8 * s, ph);
            char* Ast = smem + s * DN_STAGE;
#pragma unroll
            for (int i = 0; i < 4; i++) {
                int row = base + 32 * i;
                *(uint4*)(Ast + row * ALDR + q * 16) = av[i];
            }
            char* Bst = Ast + DN_B;
#pragma unroll
            for (int i = 0; i < 4; i++)
                *(uint4*)(Bst + base * DBR + q * 64 + i * 16) = cvt8(bv[2*i], bv[2*i+1]);
            __syncwarp();
            if (lane == 0) mbar_arrive(mb_full + 8 * s);
            if (++s == NSTAGE) { s = 0; ph ^= 1; }
        }
    }
}

// ---------------- launch ---------------------------------------------------
extern "C" void kernel_launch(void* const* d_in, const int* in_sizes, int n_in,
                              void* d_out, int out_size) {
    const float* x   = (const float*)d_in[0];
    const float* wg  = (const float*)d_in[1];
    const float* wgp = (const float*)d_in[2];
    const float* wup = (const float*)d_in[3];
    const float* wdp = (const float*)d_in[4];
    const float* wsg = (const float*)d_in[5];
    const float* wsu = (const float*)d_in[6];
    const float* wsd = (const float*)d_in[7];
    float* out = (float*)d_out;

    cudaFuncSetAttribute(gemm_gateup,      cudaFuncAttributeMaxDynamicSharedMemorySize, GU_BYTES);
    cudaFuncSetAttribute(gemm_down<false>, cudaFuncAttributeMaxDynamicSharedMemorySize, DN_BYTES);
    cudaFuncSetAttribute(gemm_down<true>,  cudaFuncAttributeMaxDynamicSharedMemorySize, DN_BYTES);

    int tail = out_size - TT * HH;
    int init_n = (tail > EE ? tail : EE);
    init_kernel<<<(init_n + 255) / 256, 256>>>(out, out_size);

    router_kernel<<<TT / 8, 256>>>(x, wg);

    dim3 g1(FF / 64, TT / 128, EE + 1);
    gemm_gateup<<<g1, 384, GU_BYTES>>>(x, wgp, wup, wsg, wsu);

    dim3 gs2(HH / 128, TT / 128, 1);
    gemm_down<false><<<gs2, 384, DN_BYTES>>>(wsd, out);   // plain store: initializes out

    dim3 ge2(HH / 128, TT / 128, EE);
    gemm_down<true><<<ge2, 384, DN_BYTES>>>(wdp, out);    // weighted atomicAdd combine
}

// round 15
// speedup vs baseline: 1.2415x; 1.0568x over previous
#include <cuda_runtime.h>
#include <cuda_fp16.h>
#include <math.h>
#include <stdint.h>

#define TT 2048
#define HH 1024
#define FF 1024
#define EE 8

// ---------------- scratch (device globals; no allocation allowed) ----------
__device__ int    g_cnt[EE];
__device__ int    g_tok[EE][TT];
__device__ float  g_wt [EE][TT];
__device__ __half g_acth[EE][TT][FF];   // routed silu(g)*u activations fp16 (32 MB)
__device__ __half g_sacth[TT][FF];      // shared-expert activations fp16 (4 MB)

// ---------------- helpers ---------------------------------------------------
__device__ __forceinline__ uint32_t h2(float x, float y) {
    __half2 h = __floats2half2_rn(x, y);
    return *(uint32_t*)&h;
}
__device__ __forceinline__ uint4 cvt8(float4 a, float4 b) {
    return make_uint4(h2(a.x, a.y), h2(a.z, a.w), h2(b.x, b.y), h2(b.z, b.w));
}
__device__ __forceinline__ uint32_t smem_u32(const void* p) {
    uint32_t a;
    asm("{ .reg .u64 t; cvta.to.shared.u64 t, %1; cvt.u32.u64 %0, t; }"
        : "=r"(a) : "l"(p));
    return a;
}
__device__ __forceinline__ void mma16(float* c, const uint32_t* a, const uint32_t* b) {
    asm volatile(
        "mma.sync.aligned.m16n8k16.row.col.f32.f16.f16.f32 "
        "{%0,%1,%2,%3}, {%4,%5,%6,%7}, {%8,%9}, {%0,%1,%2,%3};"
        : "+f"(c[0]), "+f"(c[1]), "+f"(c[2]), "+f"(c[3])
        : "r"(a[0]), "r"(a[1]), "r"(a[2]), "r"(a[3]), "r"(b[0]), "r"(b[1]));
}
__device__ __forceinline__ void ldsm4(uint32_t* r, uint32_t addr) {
    asm volatile("ldmatrix.sync.aligned.m8n8.x4.shared.b16 {%0,%1,%2,%3}, [%4];"
        : "=r"(r[0]), "=r"(r[1]), "=r"(r[2]), "=r"(r[3]) : "r"(addr));
}
__device__ __forceinline__ void ldsm4t(uint32_t* r, uint32_t addr) {
    asm volatile("ldmatrix.sync.aligned.m8n8.x4.trans.shared.b16 {%0,%1,%2,%3}, [%4];"
        : "=r"(r[0]), "=r"(r[1]), "=r"(r[2]), "=r"(r[3]) : "r"(addr));
}
__device__ __forceinline__ void mbar_init(uint32_t a, uint32_t cnt) {
    asm volatile("mbarrier.init.shared.b64 [%0], %1;" :: "r"(a), "r"(cnt) : "memory");
}
__device__ __forceinline__ void mbar_arrive(uint32_t a) {
    asm volatile("mbarrier.arrive.shared.b64 _, [%0];" :: "r"(a) : "memory");
}
__device__ __forceinline__ void mbar_wait(uint32_t a, uint32_t parity) {
    uint32_t done;
    asm volatile("{\n\t.reg .pred p;\n\t"
                 "mbarrier.try_wait.parity.acquire.cta.shared::cta.b64 p, [%1], %2;\n\t"
                 "selp.b32 %0, 1, 0, p;\n\t}"
                 : "=r"(done) : "r"(a), "r"(parity) : "memory");
    if (!done) {
        asm volatile("{\n\t.reg .pred P1;\n\t"
                     "WL_%=:\n\t"
                     "mbarrier.try_wait.parity.acquire.cta.shared::cta.b64 P1, [%0], %1, 0x989680;\n\t"
                     "@P1 bra.uni WD_%=;\n\t"
                     "bra.uni WL_%=;\n\t"
                     "WD_%=:\n\t}"
                     :: "r"(a), "r"(parity) : "memory");
    }
}

// BK = 32. A rows: 32 fp16 = 64B padded to 80B (LDSM conflict-free).
// Gateup B rows: 64 fp16 = 128B padded to 144B. Down B rows: 128 fp16 = 256B
// padded to 272B.
#define ALDR 80
#define GBR  144
#define DBR  272
#define NSTAGE 4
#define NCHUNK 32

// gateup stage: A 128x80=10240 | Bg 32x144=4608 | Bu 4608 -> 19456
#define GU_STAGE 19456
#define GU_BG    10240
#define GU_BU    14848
#define GU_MBAR  77824    // full[4] @ +0, empty[4] @ +32
#define GU_BYTES 77888
// down stage: A 10240 | B 32x272=8704 -> 18944
#define DN_STAGE 18944
#define DN_B     10240
#define DN_MBAR  75776
#define DN_BYTES 75840

// ---------------- init: zero counters + tail (aux_loss) --------------------
__global__ void init_kernel(float* __restrict__ out, int out_size) {
    int i = blockIdx.x * blockDim.x + threadIdx.x;
    if (i < EE) g_cnt[i] = 0;
    int tail = out_size - TT * HH;
    if (i < tail) out[TT * HH + i] = 0.0f;
}

// ---------------- router ----------------------------------------------------
__global__ void router_kernel(const float* __restrict__ x,
                              const float* __restrict__ wg) {
    int warp = (blockIdx.x * blockDim.x + threadIdx.x) >> 5;
    int lane = threadIdx.x & 31;
    if (warp >= TT) return;
    const float* xr = x + (size_t)warp * HH;

    float acc[EE];
#pragma unroll
    for (int e = 0; e < EE; e++) acc[e] = 0.0f;
    for (int h = lane; h < HH; h += 32) {
        float xv = xr[h];
        const float4* w4 = (const float4*)(wg + (size_t)h * EE);
        float4 a = w4[0], b = w4[1];
        acc[0] += xv * a.x; acc[1] += xv * a.y;
        acc[2] += xv * a.z; acc[3] += xv * a.w;
        acc[4] += xv * b.x; acc[5] += xv * b.y;
        acc[6] += xv * b.z; acc[7] += xv * b.w;
    }
#pragma unroll
    for (int e = 0; e < EE; e++)
#pragma unroll
        for (int o = 16; o > 0; o >>= 1)
            acc[e] += __shfl_xor_sync(0xffffffffu, acc[e], o);

    if (lane == 0) {
        int i0 = 0; float v0 = acc[0];
#pragma unroll
        for (int e = 1; e < EE; e++) if (acc[e] > v0) { v0 = acc[e]; i0 = e; }
        int i1 = -1; float v1 = -INFINITY;
#pragma unroll
        for (int e = 0; e < EE; e++) {
            if (e == i0) continue;
            if (acc[e] > v1) { v1 = acc[e]; i1 = e; }
        }
        float ex = expf(v1 - v0);
        float inv = 1.0f / (1.0f + ex);
        int p0 = atomicAdd(&g_cnt[i0], 1);
        g_tok[i0][p0] = warp; g_wt[i0][p0] = inv;
        int p1 = atomicAdd(&g_cnt[i1], 1);
        g_tok[i1][p1] = warp; g_wt[i1][p1] = ex * inv;
    }
}

// ---------------- fused gate+up GEMM (routed + shared), fp16, BK=32 --------
// grid (FF/64, TT/128, EE+1); z==EE -> shared expert (dense rows -> g_sacth).
// 384 threads: warps 0-7 consumers (4M x 2N, warp 32x32 per matrix),
// warps 8-11 producers with cross-iteration register prefetch.
__global__ __launch_bounds__(384, 1)
void gemm_gateup(const float* __restrict__ X,
                 const float* __restrict__ Wgp,
                 const float* __restrict__ Wup,
                 const float* __restrict__ Wsg,
                 const float* __restrict__ Wsu) {
    const bool SH = (blockIdx.z == EE);
    const int e   = SH ? 0 : blockIdx.z;
    const int M   = SH ? TT : g_cnt[e];
    const int m0  = blockIdx.y * 128;
    if (m0 >= M) return;
    const int n0  = blockIdx.x * 64;

    const float* Wg = SH ? Wsg : (Wgp + (size_t)e * HH * FF);
    const float* Wu = SH ? Wsu : (Wup + (size_t)e * HH * FF);

    extern __shared__ char smem[];
    const uint32_t sbase = smem_u32(smem);
    const int tid = threadIdx.x;
    const int wid = tid >> 5, lane = tid & 31;

    const uint32_t mb_full  = sbase + GU_MBAR;
    const uint32_t mb_empty = sbase + GU_MBAR + 32;
    if (tid == 0) {
#pragma unroll
        for (int s = 0; s < NSTAGE; s++) {
            mbar_init(mb_full  + 8 * s, 4);   // 4 producer warps
            mbar_init(mb_empty + 8 * s, 8);   // 8 consumer warps
        }
    }
    __syncthreads();

    if (wid < 8) {
        // ================= consumer =================
        const int wm = wid >> 1, wn = wid & 1;
        const int grp = lane >> 2, qid = lane & 3;
        uint32_t aoff[2], boff[2];
#pragma unroll
        for (int mt = 0; mt < 2; mt++)
            aoff[mt] = (wm * 32 + mt * 16 + (lane & 15)) * ALDR + ((lane & 16) ? 16 : 0);
#pragma unroll
        for (int nb = 0; nb < 2; nb++)
            boff[nb] = (lane & 15) * GBR + (wn * 32 + nb * 16) * 2 + ((lane & 16) ? 16 : 0);

        float cg[2][4][4], cu[2][4][4];
#pragma unroll
        for (int mt = 0; mt < 2; mt++)
#pragma unroll
            for (int nt = 0; nt < 4; nt++)
#pragma unroll
                for (int i = 0; i < 4; i++) { cg[mt][nt][i] = 0.0f; cu[mt][nt][i] = 0.0f; }

        int s = 0, ph = 0;
        for (int c = 0; c < NCHUNK; c++) {
            mbar_wait(mb_full + 8 * s, ph);
            const uint32_t Ab = sbase + s * GU_STAGE;
            const uint32_t Gb = Ab + GU_BG;
            const uint32_t Ub = Ab + GU_BU;
#pragma unroll
            for (int ks = 0; ks < 2; ks++) {     // two k16 steps
                uint32_t a[2][4];
                ldsm4(a[0], Ab + aoff[0] + ks * 32);
                ldsm4(a[1], Ab + aoff[1] + ks * 32);
#pragma unroll
                for (int nb = 0; nb < 2; nb++) {
                    uint32_t bg[4], bu[4];
                    ldsm4t(bg, Gb + boff[nb] + ks * 16 * GBR);
                    mma16(cg[0][nb * 2 + 0], a[0], &bg[0]);
                    mma16(cg[0][nb * 2 + 1], a[0], &bg[2]);
                    mma16(cg[1][nb * 2 + 0], a[1], &bg[0]);
                    mma16(cg[1][nb * 2 + 1], a[1], &bg[2]);
                    ldsm4t(bu, Ub + boff[nb] + ks * 16 * GBR);
                    mma16(cu[0][nb * 2 + 0], a[0], &bu[0]);
                    mma16(cu[0][nb * 2 + 1], a[0], &bu[2]);
                    mma16(cu[1][nb * 2 + 0], a[1], &bu[0]);
                    mma16(cu[1][nb * 2 + 1], a[1], &bu[2]);
                }
            }
            __syncwarp();
            if (lane == 0) mbar_arrive(mb_empty + 8 * s);
            if (++s == NSTAGE) { s = 0; ph ^= 1; }
        }

        // epilogue: silu(g)*u -> fp16
#pragma unroll
        for (int mt = 0; mt < 2; mt++) {
#pragma unroll
            for (int half = 0; half < 2; half++) {
                int m = m0 + wm * 32 + mt * 16 + grp + half * 8;
                if (m >= M) continue;
                __half* orow = SH ? &g_sacth[m][0] : &g_acth[e][m][0];
#pragma unroll
                for (int nt = 0; nt < 4; nt++) {
                    int c0 = n0 + wn * 32 + nt * 8 + 2 * qid;
                    float g0 = cg[mt][nt][half * 2 + 0], u0 = cu[mt][nt][half * 2 + 0];
                    float g1 = cg[mt][nt][half * 2 + 1], u1 = cu[mt][nt][half * 2 + 1];
                    float o0 = (g0 / (1.0f + expf(-g0))) * u0;
                    float o1 = (g1 / (1.0f + expf(-g1))) * u1;
                    *(uint32_t*)&orow[c0] = h2(o0, o1);
                }
            }
        }
    } else {
        // ========= producer (128 threads, cross-iteration prefetch) =========
        const int ptid = tid - 256;           // 0..127
        const int base = ptid >> 2;           // 0..31
        const int q    = ptid & 3;

        const float* ap[4];
#pragma unroll
        for (int i = 0; i < 4; i++) {
            int r = m0 + base + 32 * i;
            if (r < M) {
                int tok = SH ? r : g_tok[e][r];
                ap[i] = X + (size_t)tok * HH + q * 8;
            } else ap[i] = nullptr;
        }
        const float* gp = Wg + (size_t)base * FF + n0 + q * 16;
        const float* up = Wu + (size_t)base * FF + n0 + q * 16;

        float4 av[2][4][2], gv[2][4], uv[2][4];   // double register buffers

        // load chunk c into buffer b
        auto loadc = [&](int c, int b) {
            const int kk = c * 32;
#pragma unroll
            for (int i = 0; i < 4; i++) {
                av[b][i][0] = ap[i] ? *(const float4*)(ap[i] + kk)     : make_float4(0,0,0,0);
                av[b][i][1] = ap[i] ? *(const float4*)(ap[i] + kk + 4) : make_float4(0,0,0,0);
            }
#pragma unroll
            for (int i = 0; i < 4; i++) {
                gv[b][i] = *(const float4*)(gp + (size_t)kk * FF + 4 * i);
                uv[b][i] = *(const float4*)(up + (size_t)kk * FF + 4 * i);
            }
        };

        loadc(0, 0);
        int s = 0, ph = 1;   // first empty-wait passes immediately
#pragma unroll 2
        for (int c = 0; c < NCHUNK; c++) {
            const int b = c & 1;
            if (c + 1 < NCHUNK) loadc(c + 1, b ^ 1);   // prefetch next chunk
            mbar_wait(mb_empty + 8 * s, ph);
            char* Ast = smem + s * GU_STAGE;
#pragma unroll
            for (int i = 0; i < 4; i++) {
                int row = base + 32 * i;
                *(uint4*)(Ast + row * ALDR + q * 16) = cvt8(av[b][i][0], av[b][i][1]);
            }
            char* Gst = Ast + GU_BG;
            char* Ust = Ast + GU_BU;
#pragma unroll
            for (int i = 0; i < 2; i++) {
                *(uint4*)(Gst + base * GBR + q * 32 + i * 16) = cvt8(gv[b][2*i], gv[b][2*i+1]);
                *(uint4*)(Ust + base * GBR + q * 32 + i * 16) = cvt8(uv[b][2*i], uv[b][2*i+1]);
            }
            __syncwarp();
            if (lane == 0) mbar_arrive(mb_full + 8 * s);
            if (++s == NSTAGE) { s = 0; ph ^= 1; }
        }
    }
}

// ---------------- down-proj GEMM, fp16 A, BK=32 ----------------------------
// EXPERT: A = g_acth[e], weighted atomicAdd. !EXPERT: A = g_sacth, plain
// store (initializes out). Block 128(M) x 128(N), consumers 4M x 2N (32x64).
template <bool EXPERT>
__global__ __launch_bounds__(384, 1)
void gemm_down(const float* __restrict__ Wd_all,
               float* __restrict__ out) {
    const int e  = EXPERT ? blockIdx.z : 0;
    const int M  = EXPERT ? g_cnt[e] : TT;
    const int m0 = blockIdx.y * 128;
    if (m0 >= M) return;
    const int n0 = blockIdx.x * 128;

    const float*  Wd     = Wd_all + (EXPERT ? (size_t)e * FF * HH : 0);
    const __half* Asrc_h = EXPERT ? &g_acth[e][0][0] : &g_sacth[0][0];

    extern __shared__ char smem[];
    const uint32_t sbase = smem_u32(smem);
    const int tid = threadIdx.x;
    const int wid = tid >> 5, lane = tid & 31;

    const uint32_t mb_full  = sbase + DN_MBAR;
    const uint32_t mb_empty = sbase + DN_MBAR + 32;
    if (tid == 0) {
#pragma unroll
        for (int s = 0; s < NSTAGE; s++) {
            mbar_init(mb_full  + 8 * s, 4);
            mbar_init(mb_empty + 8 * s, 8);
        }
    }
    __syncthreads();

    if (wid < 8) {
        // ================= consumer =================
        const int wm = wid >> 1, wn = wid & 1;
        const int grp = lane >> 2, qid = lane & 3;
        uint32_t aoff[2], boff[4];
#pragma unroll
        for (int mt = 0; mt < 2; mt++)
            aoff[mt] = (wm * 32 + mt * 16 + (lane & 15)) * ALDR + ((lane & 16) ? 16 : 0);
#pragma unroll
        for (int nb = 0; nb < 4; nb++)
            boff[nb] = (lane & 15) * DBR + (wn * 64 + nb * 16) * 2 + ((lane & 16) ? 16 : 0);

        float cc[2][8][4];
#pragma unroll
        for (int mt = 0; mt < 2; mt++)
#pragma unroll
            for (int nt = 0; nt < 8; nt++)
#pragma unroll
                for (int i = 0; i < 4; i++) cc[mt][nt][i] = 0.0f;

        int s = 0, ph = 0;
        for (int c = 0; c < NCHUNK; c++) {
            mbar_wait(mb_full + 8 * s, ph);
            const uint32_t Ab = sbase + s * DN_STAGE;
            const uint32_t Bb = Ab + DN_B;
#pragma unroll
            for (int ks = 0; ks < 2; ks++) {
                uint32_t a[2][4];
                ldsm4(a[0], Ab + aoff[0] + ks * 32);
                ldsm4(a[1], Ab + aoff[1] + ks * 32);
#pragma unroll
                for (int nb = 0; nb < 4; nb++) {
                    uint32_t b_[4];
                    ldsm4t(b_, Bb + boff[nb] + ks * 16 * DBR);
                    mma16(cc[0][nb * 2 + 0], a[0], &b_[0]);
                    mma16(cc[0][nb * 2 + 1], a[0], &b_[2]);
                    mma16(cc[1][nb * 2 + 0], a[1], &b_[0]);
                    mma16(cc[1][nb * 2 + 1], a[1], &b_[2]);
                }
            }
            __syncwarp();
            if (lane == 0) mbar_arrive(mb_empty + 8 * s);
            if (++s == NSTAGE) { s = 0; ph ^= 1; }
        }

#pragma unroll
        for (int mt = 0; mt < 2; mt++) {
#pragma unroll
            for (int half = 0; half < 2; half++) {
                int m = m0 + wm * 32 + mt * 16 + grp + half * 8;
                if (m >= M) continue;
                if (EXPERT) {
                    int tok = g_tok[e][m];
                    float w = g_wt[e][m];
                    float* orow = out + (size_t)tok * HH;
#pragma unroll
                    for (int nt = 0; nt < 8; nt++) {
                        int c0 = n0 + wn * 64 + nt * 8 + 2 * qid;
                        atomicAdd(&orow[c0],     w * cc[mt][nt][half * 2 + 0]);
                        atomicAdd(&orow[c0 + 1], w * cc[mt][nt][half * 2 + 1]);
                    }
                } else {
                    float* orow = out + (size_t)m * HH;
#pragma unroll
                    for (int nt = 0; nt < 8; nt++) {
                        int c0 = n0 + wn * 64 + nt * 8 + 2 * qid;
                        float2 o = make_float2(cc[mt][nt][half * 2 + 0],
                                               cc[mt][nt][half * 2 + 1]);
                        *(float2*)&orow[c0] = o;
                    }
                }
            }
        }
    } else {
        // ========= producer (128 threads, cross-iteration prefetch) =========
        const int ptid = tid - 256;
        const int base = ptid >> 2;           // 0..31
        const int q    = ptid & 3;

        const __half* ap[4];
#pragma unroll
        for (int i = 0; i < 4; i++) {
            int r = m0 + base + 32 * i;
            ap[i] = (r < M) ? (Asrc_h + (size_t)r * FF + q * 8) : nullptr;
        }
        const float* wp = Wd + (size_t)base * HH + n0 + q * 32;

        uint4  av[2][4];
        float4 bv[2][8];

        auto loadc = [&](int c, int b) {
            const int kk = c * 32;
#pragma unroll
            for (int i = 0; i < 4; i++)
                av[b][i] = ap[i] ? *(const uint4*)(ap[i] + kk) : make_uint4(0, 0, 0, 0);
#pragma unroll
            for (int i = 0; i < 8; i++)
                bv[b][i] = *(const float4*)(wp + (size_t)kk * HH + 4 * i);
        };

        loadc(0, 0);
        int s = 0, ph = 1;
#pragma unroll 2
        for (int c = 0; c < NCHUNK; c++) {
            const int b = c & 1;
            if (c + 1 < NCHUNK) loadc(c + 1, b ^ 1);   // prefetch next chunk
            mbar_wait(mb_empty + 8 * s, ph);
            char* Ast = smem + s * DN_STAGE;
#pragma unroll
            for (int i = 0; i < 4; i++) {
                int row = base + 32 * i;
                *(uint4*)(Ast + row * ALDR + q * 16) = av[b][i];
            }
            char* Bst = Ast + DN_B;
#pragma unroll
            for (int i = 0; i < 4; i++)
                *(uint4*)(Bst + base * DBR + q * 64 + i * 16) = cvt8(bv[b][2*i], bv[b][2*i+1]);
            __syncwarp();
            if (lane == 0) mbar_arrive(mb_full + 8 * s);
            if (++s == NSTAGE) { s = 0; ph ^= 1; }
        }
    }
}

// ---------------- launch ---------------------------------------------------
extern "C" void kernel_launch(void* const* d_in, const int* in_sizes, int n_in,
                              void* d_out, int out_size) {
    const float* x   = (const float*)d_in[0];
    const float* wg  = (const float*)d_in[1];
    const float* wgp = (const float*)d_in[2];
    const float* wup = (const float*)d_in[3];
    const float* wdp = (const float*)d_in[4];
    const float* wsg = (const float*)d_in[5];
    const float* wsu = (const float*)d_in[6];
    const float* wsd = (const float*)d_in[7];
    float* out = (float*)d_out;

    cudaFuncSetAttribute(gemm_gateup,      cudaFuncAttributeMaxDynamicSharedMemorySize, GU_BYTES);
    cudaFuncSetAttribute(gemm_down<false>, cudaFuncAttributeMaxDynamicSharedMemorySize, DN_BYTES);
    cudaFuncSetAttribute(gemm_down<true>,  cudaFuncAttributeMaxDynamicSharedMemorySize, DN_BYTES);

    int tail = out_size - TT * HH;
    int init_n = (tail > EE ? tail : EE);
    init_kernel<<<(init_n + 255) / 256, 256>>>(out, out_size);

    router_kernel<<<TT / 8, 256>>>(x, wg);

    dim3 g1(FF / 64, TT / 128, EE + 1);
    gemm_gateup<<<g1, 384, GU_BYTES>>>(x, wgp, wup, wsg, wsu);

    dim3 gs2(HH / 128, TT / 128, 1);
    gemm_down<false><<<gs2, 384, DN_BYTES>>>(wsd, out);   // plain store: initializes out

    dim3 ge2(HH / 128, TT / 128, EE);
    gemm_down<true><<<ge2, 384, DN_BYTES>>>(wdp, out);    // weighted atomicAdd combine
}

// round 16
// speedup vs baseline: 1.2428x; 1.0010x over previous
#include <cuda_runtime.h>
#include <cuda_fp16.h>
#include <math.h>
#include <stdint.h>

#define TT 2048
#define HH 1024
#define FF 1024
#define EE 8

// ---------------- scratch (device globals; no allocation allowed) ----------
__device__ int    g_cnt[EE];
__device__ int    g_tok[EE][TT];
__device__ float  g_wt [EE][TT];
__device__ __half g_acth[EE][TT][FF];   // routed silu(g)*u activations fp16 (32 MB)
__device__ __half g_sacth[TT][FF];      // shared-expert activations fp16 (4 MB)

// ---------------- helpers ---------------------------------------------------
__device__ __forceinline__ uint32_t h2(float x, float y) {
    __half2 h = __floats2half2_rn(x, y);
    return *(uint32_t*)&h;
}
__device__ __forceinline__ uint4 cvt8(float4 a, float4 b) {
    return make_uint4(h2(a.x, a.y), h2(a.z, a.w), h2(b.x, b.y), h2(b.z, b.w));
}
__device__ __forceinline__ uint32_t smem_u32(const void* p) {
    uint32_t a;
    asm("{ .reg .u64 t; cvta.to.shared.u64 t, %1; cvt.u32.u64 %0, t; }"
        : "=r"(a) : "l"(p));
    return a;
}
__device__ __forceinline__ void mma16(float* c, const uint32_t* a, const uint32_t* b) {
    asm volatile(
        "mma.sync.aligned.m16n8k16.row.col.f32.f16.f16.f32 "
        "{%0,%1,%2,%3}, {%4,%5,%6,%7}, {%8,%9}, {%0,%1,%2,%3};"
        : "+f"(c[0]), "+f"(c[1]), "+f"(c[2]), "+f"(c[3])
        : "r"(a[0]), "r"(a[1]), "r"(a[2]), "r"(a[3]), "r"(b[0]), "r"(b[1]));
}
__device__ __forceinline__ void ldsm4(uint32_t* r, uint32_t addr) {
    asm volatile("ldmatrix.sync.aligned.m8n8.x4.shared.b16 {%0,%1,%2,%3}, [%4];"
        : "=r"(r[0]), "=r"(r[1]), "=r"(r[2]), "=r"(r[3]) : "r"(addr));
}
__device__ __forceinline__ void ldsm4t(uint32_t* r, uint32_t addr) {
    asm volatile("ldmatrix.sync.aligned.m8n8.x4.trans.shared.b16 {%0,%1,%2,%3}, [%4];"
        : "=r"(r[0]), "=r"(r[1]), "=r"(r[2]), "=r"(r[3]) : "r"(addr));
}
__device__ __forceinline__ void mbar_init(uint32_t a, uint32_t cnt) {
    asm volatile("mbarrier.init.shared.b64 [%0], %1;" :: "r"(a), "r"(cnt) : "memory");
}
__device__ __forceinline__ void mbar_arrive(uint32_t a) {
    asm volatile("mbarrier.arrive.shared.b64 _, [%0];" :: "r"(a) : "memory");
}
__device__ __forceinline__ void mbar_wait(uint32_t a, uint32_t parity) {
    uint32_t done;
    asm volatile("{\n\t.reg .pred p;\n\t"
                 "mbarrier.try_wait.parity.acquire.cta.shared::cta.b64 p, [%1], %2;\n\t"
                 "selp.b32 %0, 1, 0, p;\n\t}"
                 : "=r"(done) : "r"(a), "r"(parity) : "memory");
    if (!done) {
        asm volatile("{\n\t.reg .pred P1;\n\t"
                     "WL_%=:\n\t"
                     "mbarrier.try_wait.parity.acquire.cta.shared::cta.b64 P1, [%0], %1, 0x989680;\n\t"
                     "@P1 bra.uni WD_%=;\n\t"
                     "bra.uni WL_%=;\n\t"
                     "WD_%=:\n\t}"
                     :: "r"(a), "r"(parity) : "memory");
    }
}

// BK = 32. A rows: 32 fp16 = 64B padded to 80B (LDSM conflict-free).
// Gateup B rows: 64 fp16 = 128B padded to 144B. Down B rows: 128 fp16 = 256B
// padded to 272B.
#define ALDR 80
#define GBR  144
#define DBR  272
#define NSTAGE 4
#define NCHUNK 32

// gateup stage: A 128x80=10240 | Bg 32x144=4608 | Bu 4608 -> 19456
#define GU_STAGE 19456
#define GU_BG    10240
#define GU_BU    14848
#define GU_MBAR  77824    // full[4] @ +0, empty[4] @ +32
#define GU_BYTES 77888
// down stage: A 10240 | B 32x272=8704 -> 18944
#define DN_STAGE 18944
#define DN_B     10240
#define DN_MBAR  75776
#define DN_BYTES 75840

// ---------------- init: zero counters + tail (aux_loss) --------------------
__global__ void init_kernel(float* __restrict__ out, int out_size) {
    int i = blockIdx.x * blockDim.x + threadIdx.x;
    if (i < EE) g_cnt[i] = 0;
    int tail = out_size - TT * HH;
    if (i < tail) out[TT * HH + i] = 0.0f;
}

// ---------------- router ----------------------------------------------------
__global__ void router_kernel(const float* __restrict__ x,
                              const float* __restrict__ wg) {
    int warp = (blockIdx.x * blockDim.x + threadIdx.x) >> 5;
    int lane = threadIdx.x & 31;
    if (warp >= TT) return;
    const float* xr = x + (size_t)warp * HH;

    float acc[EE];
#pragma unroll
    for (int e = 0; e < EE; e++) acc[e] = 0.0f;
    for (int h = lane; h < HH; h += 32) {
        float xv = xr[h];
        const float4* w4 = (const float4*)(wg + (size_t)h * EE);
        float4 a = w4[0], b = w4[1];
        acc[0] += xv * a.x; acc[1] += xv * a.y;
        acc[2] += xv * a.z; acc[3] += xv * a.w;
        acc[4] += xv * b.x; acc[5] += xv * b.y;
        acc[6] += xv * b.z; acc[7] += xv * b.w;
    }
#pragma unroll
    for (int e = 0; e < EE; e++)
#pragma unroll
        for (int o = 16; o > 0; o >>= 1)
            acc[e] += __shfl_xor_sync(0xffffffffu, acc[e], o);

    if (lane == 0) {
        int i0 = 0; float v0 = acc[0];
#pragma unroll
        for (int e = 1; e < EE; e++) if (acc[e] > v0) { v0 = acc[e]; i0 = e; }
        int i1 = -1; float v1 = -INFINITY;
#pragma unroll
        for (int e = 0; e < EE; e++) {
            if (e == i0) continue;
            if (acc[e] > v1) { v1 = acc[e]; i1 = e; }
        }
        float ex = expf(v1 - v0);
        float inv = 1.0f / (1.0f + ex);
        int p0 = atomicAdd(&g_cnt[i0], 1);
        g_tok[i0][p0] = warp; g_wt[i0][p0] = inv;
        int p1 = atomicAdd(&g_cnt[i1], 1);
        g_tok[i1][p1] = warp; g_wt[i1][p1] = ex * inv;
    }
}

// ---------------- fused gate+up GEMM (routed + shared), fp16, BK=32 --------
// grid (FF/64, TT/128, EE+1); z==EE -> shared expert (dense rows -> g_sacth).
// 384 threads: warps 0-7 consumers (batched LDSM then MMA burst),
// warps 8-11 producers with cross-iteration register prefetch.
__global__ __launch_bounds__(384, 1)
void gemm_gateup(const float* __restrict__ X,
                 const float* __restrict__ Wgp,
                 const float* __restrict__ Wup,
                 const float* __restrict__ Wsg,
                 const float* __restrict__ Wsu) {
    const bool SH = (blockIdx.z == EE);
    const int e   = SH ? 0 : blockIdx.z;
    const int M   = SH ? TT : g_cnt[e];
    const int m0  = blockIdx.y * 128;
    if (m0 >= M) return;
    const int n0  = blockIdx.x * 64;

    const float* Wg = SH ? Wsg : (Wgp + (size_t)e * HH * FF);
    const float* Wu = SH ? Wsu : (Wup + (size_t)e * HH * FF);

    extern __shared__ char smem[];
    const uint32_t sbase = smem_u32(smem);
    const int tid = threadIdx.x;
    const int wid = tid >> 5, lane = tid & 31;

    const uint32_t mb_full  = sbase + GU_MBAR;
    const uint32_t mb_empty = sbase + GU_MBAR + 32;
    if (tid == 0) {
#pragma unroll
        for (int s = 0; s < NSTAGE; s++) {
            mbar_init(mb_full  + 8 * s, 4);   // 4 producer warps
            mbar_init(mb_empty + 8 * s, 8);   // 8 consumer warps
        }
    }
    __syncthreads();

    if (wid < 8) {
        // ================= consumer =================
        const int wm = wid >> 1, wn = wid & 1;
        const int grp = lane >> 2, qid = lane & 3;
        uint32_t aoff[2], boff[2];
#pragma unroll
        for (int mt = 0; mt < 2; mt++)
            aoff[mt] = (wm * 32 + mt * 16 + (lane & 15)) * ALDR + ((lane & 16) ? 16 : 0);
#pragma unroll
        for (int nb = 0; nb < 2; nb++)
            boff[nb] = (lane & 15) * GBR + (wn * 32 + nb * 16) * 2 + ((lane & 16) ? 16 : 0);

        float cg[2][4][4], cu[2][4][4];
#pragma unroll
        for (int mt = 0; mt < 2; mt++)
#pragma unroll
            for (int nt = 0; nt < 4; nt++)
#pragma unroll
                for (int i = 0; i < 4; i++) { cg[mt][nt][i] = 0.0f; cu[mt][nt][i] = 0.0f; }

        int s = 0, ph = 0;
        for (int c = 0; c < NCHUNK; c++) {
            mbar_wait(mb_full + 8 * s, ph);
            const uint32_t Ab = sbase + s * GU_STAGE;
            const uint32_t Gb = Ab + GU_BG;
            const uint32_t Ub = Ab + GU_BU;
            // ---- batched fragment loads (12 LDSM back-to-back) ----
            uint32_t a[2][2][4], bg[2][2][4], bu[2][2][4];
#pragma unroll
            for (int ks = 0; ks < 2; ks++) {
                ldsm4(a[ks][0], Ab + aoff[0] + ks * 32);
                ldsm4(a[ks][1], Ab + aoff[1] + ks * 32);
                ldsm4t(bg[ks][0], Gb + boff[0] + ks * 16 * GBR);
                ldsm4t(bg[ks][1], Gb + boff[1] + ks * 16 * GBR);
                ldsm4t(bu[ks][0], Ub + boff[0] + ks * 16 * GBR);
                ldsm4t(bu[ks][1], Ub + boff[1] + ks * 16 * GBR);
            }
            // ---- MMA burst (32) ----
#pragma unroll
            for (int ks = 0; ks < 2; ks++)
#pragma unroll
                for (int nb = 0; nb < 2; nb++) {
                    mma16(cg[0][nb * 2 + 0], a[ks][0], &bg[ks][nb][0]);
                    mma16(cg[0][nb * 2 + 1], a[ks][0], &bg[ks][nb][2]);
                    mma16(cg[1][nb * 2 + 0], a[ks][1], &bg[ks][nb][0]);
                    mma16(cg[1][nb * 2 + 1], a[ks][1], &bg[ks][nb][2]);
                    mma16(cu[0][nb * 2 + 0], a[ks][0], &bu[ks][nb][0]);
                    mma16(cu[0][nb * 2 + 1], a[ks][0], &bu[ks][nb][2]);
                    mma16(cu[1][nb * 2 + 0], a[ks][1], &bu[ks][nb][0]);
                    mma16(cu[1][nb * 2 + 1], a[ks][1], &bu[ks][nb][2]);
                }
            __syncwarp();
            if (lane == 0) mbar_arrive(mb_empty + 8 * s);
            if (++s == NSTAGE) { s = 0; ph ^= 1; }
        }

        // epilogue: silu(g)*u -> fp16
#pragma unroll
        for (int mt = 0; mt < 2; mt++) {
#pragma unroll
            for (int half = 0; half < 2; half++) {
                int m = m0 + wm * 32 + mt * 16 + grp + half * 8;
                if (m >= M) continue;
                __half* orow = SH ? &g_sacth[m][0] : &g_acth[e][m][0];
#pragma unroll
                for (int nt = 0; nt < 4; nt++) {
                    int c0 = n0 + wn * 32 + nt * 8 + 2 * qid;
                    float g0 = cg[mt][nt][half * 2 + 0], u0 = cu[mt][nt][half * 2 + 0];
                    float g1 = cg[mt][nt][half * 2 + 1], u1 = cu[mt][nt][half * 2 + 1];
                    float o0 = (g0 / (1.0f + expf(-g0))) * u0;
                    float o1 = (g1 / (1.0f + expf(-g1))) * u1;
                    *(uint32_t*)&orow[c0] = h2(o0, o1);
                }
            }
        }
    } else {
        // ========= producer (128 threads, cross-iteration prefetch) =========
        const int ptid = tid - 256;           // 0..127
        const int base = ptid >> 2;           // 0..31
        const int q    = ptid & 3;

        const float* ap[4];
#pragma unroll
        for (int i = 0; i < 4; i++) {
            int r = m0 + base + 32 * i;
            if (r < M) {
                int tok = SH ? r : g_tok[e][r];
                ap[i] = X + (size_t)tok * HH + q * 8;
            } else ap[i] = nullptr;
        }
        const float* gp = Wg + (size_t)base * FF + n0 + q * 16;
        const float* up = Wu + (size_t)base * FF + n0 + q * 16;

        float4 av[2][4][2], gv[2][4], uv[2][4];   // double register buffers

        auto loadc = [&](int c, int b) {
            const int kk = c * 32;
#pragma unroll
            for (int i = 0; i < 4; i++) {
                av[b][i][0] = ap[i] ? *(const float4*)(ap[i] + kk)     : make_float4(0,0,0,0);
                av[b][i][1] = ap[i] ? *(const float4*)(ap[i] + kk + 4) : make_float4(0,0,0,0);
            }
#pragma unroll
            for (int i = 0; i < 4; i++) {
                gv[b][i] = *(const float4*)(gp + (size_t)kk * FF + 4 * i);
                uv[b][i] = *(const float4*)(up + (size_t)kk * FF + 4 * i);
            }
        };

        loadc(0, 0);
        int s = 0, ph = 1;   // first empty-wait passes immediately
#pragma unroll 2
        for (int c = 0; c < NCHUNK; c++) {
            const int b = c & 1;
            if (c + 1 < NCHUNK) loadc(c + 1, b ^ 1);   // prefetch next chunk
            mbar_wait(mb_empty + 8 * s, ph);
            char* Ast = smem + s * GU_STAGE;
#pragma unroll
            for (int i = 0; i < 4; i++) {
                int row = base + 32 * i;
                *(uint4*)(Ast + row * ALDR + q * 16) = cvt8(av[b][i][0], av[b][i][1]);
            }
            char* Gst = Ast + GU_BG;
            char* Ust = Ast + GU_BU;
#pragma unroll
            for (int i = 0; i < 2; i++) {
                *(uint4*)(Gst + base * GBR + q * 32 + i * 16) = cvt8(gv[b][2*i], gv[b][2*i+1]);
                *(uint4*)(Ust + base * GBR + q * 32 + i * 16) = cvt8(uv[b][2*i], uv[b][2*i+1]);
            }
            __syncwarp();
            if (lane == 0) mbar_arrive(mb_full + 8 * s);
            if (++s == NSTAGE) { s = 0; ph ^= 1; }
        }
    }
}

// ---------------- down-proj GEMM, fp16 A, BK=32 ----------------------------
// EXPERT: A = g_acth[e], weighted atomicAdd. !EXPERT: A = g_sacth, plain
// store (initializes out). Block 128(M) x 128(N), consumers 4M x 2N (32x64).
template <bool EXPERT>
__global__ __launch_bounds__(384, 1)
void gemm_down(const float* __restrict__ Wd_all,
               float* __restrict__ out) {
    const int e  = EXPERT ? blockIdx.z : 0;
    const int M  = EXPERT ? g_cnt[e] : TT;
    const int m0 = blockIdx.y * 128;
    if (m0 >= M) return;
    const int n0 = blockIdx.x * 128;

    const float*  Wd     = Wd_all + (EXPERT ? (size_t)e * FF * HH : 0);
    const __half* Asrc_h = EXPERT ? &g_acth[e][0][0] : &g_sacth[0][0];

    extern __shared__ char smem[];
    const uint32_t sbase = smem_u32(smem);
    const int tid = threadIdx.x;
    const int wid = tid >> 5, lane = tid & 31;

    const uint32_t mb_full  = sbase + DN_MBAR;
    const uint32_t mb_empty = sbase + DN_MBAR + 32;
    if (tid == 0) {
#pragma unroll
        for (int s = 0; s < NSTAGE; s++) {
            mbar_init(mb_full  + 8 * s, 4);
            mbar_init(mb_empty + 8 * s, 8);
        }
    }
    __syncthreads();

    if (wid < 8) {
        // ================= consumer =================
        const int wm = wid >> 1, wn = wid & 1;
        const int grp = lane >> 2, qid = lane & 3;
        uint32_t aoff[2], boff[4];
#pragma unroll
        for (int mt = 0; mt < 2; mt++)
            aoff[mt] = (wm * 32 + mt * 16 + (lane & 15)) * ALDR + ((lane & 16) ? 16 : 0);
#pragma unroll
        for (int nb = 0; nb < 4; nb++)
            boff[nb] = (lane & 15) * DBR + (wn * 64 + nb * 16) * 2 + ((lane & 16) ? 16 : 0);

        float cc[2][8][4];
#pragma unroll
        for (int mt = 0; mt < 2; mt++)
#pragma unroll
            for (int nt = 0; nt < 8; nt++)
#pragma unroll
                for (int i = 0; i < 4; i++) cc[mt][nt][i] = 0.0f;

        int s = 0, ph = 0;
        for (int c = 0; c < NCHUNK; c++) {
            mbar_wait(mb_full + 8 * s, ph);
            const uint32_t Ab = sbase + s * DN_STAGE;
            const uint32_t Bb = Ab + DN_B;
            // ---- batched fragment loads (12 LDSM back-to-back) ----
            uint32_t a[2][2][4], b_[2][4][4];
#pragma unroll
            for (int ks = 0; ks < 2; ks++) {
                ldsm4(a[ks][0], Ab + aoff[0] + ks * 32);
                ldsm4(a[ks][1], Ab + aoff[1] + ks * 32);
#pragma unroll
                for (int nb = 0; nb < 4; nb++)
                    ldsm4t(b_[ks][nb], Bb + boff[nb] + ks * 16 * DBR);
            }
            // ---- MMA burst (32) ----
#pragma unroll
            for (int ks = 0; ks < 2; ks++)
#pragma unroll
                for (int nb = 0; nb < 4; nb++) {
                    mma16(cc[0][nb * 2 + 0], a[ks][0], &b_[ks][nb][0]);
                    mma16(cc[0][nb * 2 + 1], a[ks][0], &b_[ks][nb][2]);
                    mma16(cc[1][nb * 2 + 0], a[ks][1], &b_[ks][nb][0]);
                    mma16(cc[1][nb * 2 + 1], a[ks][1], &b_[ks][nb][2]);
                }
            __syncwarp();
            if (lane == 0) mbar_arrive(mb_empty + 8 * s);
            if (++s == NSTAGE) { s = 0; ph ^= 1; }
        }

#pragma unroll
        for (int mt = 0; mt < 2; mt++) {
#pragma unroll
            for (int half = 0; half < 2; half++) {
                int m = m0 + wm * 32 + mt * 16 + grp + half * 8;
                if (m >= M) continue;
                if (EXPERT) {
                    int tok = g_tok[e][m];
                    float w = g_wt[e][m];
                    float* orow = out + (size_t)tok * HH;
#pragma unroll
                    for (int nt = 0; nt < 8; nt++) {
                        int c0 = n0 + wn * 64 + nt * 8 + 2 * qid;
                        atomicAdd(&orow[c0],     w * cc[mt][nt][half * 2 + 0]);
                        atomicAdd(&orow[c0 + 1], w * cc[mt][nt][half * 2 + 1]);
                    }
                } else {
                    float* orow = out + (size_t)m * HH;
#pragma unroll
                    for (int nt = 0; nt < 8; nt++) {
                        int c0 = n0 + wn * 64 + nt * 8 + 2 * qid;
                        float2 o = make_float2(cc[mt][nt][half * 2 + 0],
                                               cc[mt][nt][half * 2 + 1]);
                        *(float2*)&orow[c0] = o;
                    }
                }
            }
        }
    } else {
        // ========= producer (128 threads, cross-iteration prefetch) =========
        const int ptid = tid - 256;
        const int base = ptid >> 2;           // 0..31
        const int q    = ptid & 3;

        const __half* ap[4];
#pragma unroll
        for (int i = 0; i < 4; i++) {
            int r = m0 + base + 32 * i;
            ap[i] = (r < M) ? (Asrc_h + (size_t)r * FF + q * 8) : nullptr;
        }
        const float* wp = Wd + (size_t)base * HH + n0 + q * 32;

        uint4  av[2][4];
        float4 bv[2][8];

        auto loadc = [&](int c, int b) {
            const int kk = c * 32;
#pragma unroll
            for (int i = 0; i < 4; i++)
                av[b][i] = ap[i] ? *(const uint4*)(ap[i] + kk) : make_uint4(0, 0, 0, 0);
#pragma unroll
            for (int i = 0; i < 8; i++)
                bv[b][i] = *(const float4*)(wp + (size_t)kk * HH + 4 * i);
        };

        loadc(0, 0);
        int s = 0, ph = 1;
#pragma unroll 2
        for (int c = 0; c < NCHUNK; c++) {
            const int b = c & 1;
            if (c + 1 < NCHUNK) loadc(c + 1, b ^ 1);   // prefetch next chunk
            mbar_wait(mb_empty + 8 * s, ph);
            char* Ast = smem + s * DN_STAGE;
#pragma unroll
            for (int i = 0; i < 4; i++) {
                int row = base + 32 * i;
                *(uint4*)(Ast + row * ALDR + q * 16) = av[b][i];
            }
            char* Bst = Ast + DN_B;
#pragma unroll
            for (int i = 0; i < 4; i++)
                *(uint4*)(Bst + base * DBR + q * 64 + i * 16) = cvt8(bv[b][2*i], bv[b][2*i+1]);
            __syncwarp();
            if (lane == 0) mbar_arrive(mb_full + 8 * s);
            if (++s == NSTAGE) { s = 0; ph ^= 1; }
        }
    }
}

// ---------------- launch ---------------------------------------------------
extern "C" void kernel_launch(void* const* d_in, const int* in_sizes, int n_in,
                              void* d_out, int out_size) {
    const float* x   = (const float*)d_in[0];
    const float* wg  = (const float*)d_in[1];
    const float* wgp = (const float*)d_in[2];
    const float* wup = (const float*)d_in[3];
    const float* wdp = (const float*)d_in[4];
    const float* wsg = (const float*)d_in[5];
    const float* wsu = (const float*)d_in[6];
    const float* wsd = (const float*)d_in[7];
    float* out = (float*)d_out;

    cudaFuncSetAttribute(gemm_gateup,      cudaFuncAttributeMaxDynamicSharedMemorySize, GU_BYTES);
    cudaFuncSetAttribute(gemm_down<false>, cudaFuncAttributeMaxDynamicSharedMemorySize, DN_BYTES);
    cudaFuncSetAttribute(gemm_down<true>,  cudaFuncAttributeMaxDynamicSharedMemorySize, DN_BYTES);

    int tail = out_size - TT * HH;
    int init_n = (tail > EE ? tail : EE);
    init_kernel<<<(init_n + 255) / 256, 256>>>(out, out_size);

    router_kernel<<<TT / 8, 256>>>(x, wg);

    dim3 g1(FF / 64, TT / 128, EE + 1);
    gemm_gateup<<<g1, 384, GU_BYTES>>>(x, wgp, wup, wsg, wsu);

    dim3 gs2(HH / 128, TT / 128, 1);
    gemm_down<false><<<gs2, 384, DN_BYTES>>>(wsd, out);   // plain store: initializes out

    dim3 ge2(HH / 128, TT / 128, EE);
    gemm_down<true><<<ge2, 384, DN_BYTES>>>(wdp, out);    // weighted atomicAdd combine
}